// round 1
// baseline (speedup 1.0000x reference)
#include <cuda_runtime.h>
#include <math.h>

#define EMB   768
#define NDIM  128
#define MROWS 1024
#define XROW  (3*EMB + 2)   // 2306
#define WPITCH 132          // padded smem pitch (4-way max store conflict, float4-aligned)

// scratch (device bss, no allocations)
__device__ float g_P[3 * MROWS * EMB];   // pooled p1 | p2 | qv
__device__ float g_H[3 * MROWS * EMB];   // after W1
__device__ float g_Z[3 * MROWS * EMB];   // after W2 + relu

// dynamic smem layout for attend kernel (floats)
#define S_AQ   0
#define S_AP   16384
#define S_WT   32768
#define S_XT   (S_WT + 32*WPITCH)        // 36992
#define S_VA   (S_XT + 32*128)           // 41088
#define S_BETA (S_VA + 128)
#define S_RED  (S_BETA + 128)
#define SMEM_FLOATS (S_RED + 16)
#define SMEM_BYTES (SMEM_FLOATS * 4)     // ~165.4 KB

// C[128x128] = Wa[:, w_eoff : w_eoff+768] @ X-slab(768 x 128), fp32 FFMA, 8x8/thread
__device__ __forceinline__ void gemm_128x128(
    float* __restrict__ C, float* __restrict__ Wt, float* __restrict__ Xt,
    const float* __restrict__ Wa, const float* __restrict__ X,
    int w_eoff, size_t x_base, int tid, int tx, int ty)
{
    float acc[8][8];
    #pragma unroll
    for (int i = 0; i < 8; ++i)
        #pragma unroll
        for (int j = 0; j < 8; ++j) acc[i][j] = 0.f;

    for (int k0 = 0; k0 < EMB; k0 += 32) {
        // W tile: gmem-coalesced along e, transposed into smem [kk][k]
        #pragma unroll
        for (int l = 0; l < 16; ++l) {
            int idx = tid + l * 256;
            int k = idx >> 5, kk = idx & 31;
            Wt[kk * WPITCH + k] = Wa[k * (2*EMB) + w_eoff + k0 + kk];
        }
        // X tile: float4, fully coalesced, conflict-free smem
        const float4* Xg = reinterpret_cast<const float4*>(X + x_base + (size_t)k0 * NDIM);
        #pragma unroll
        for (int l = 0; l < 4; ++l) {
            int idx = tid + l * 256;           // 0..1023 float4s
            reinterpret_cast<float4*>(Xt)[idx] = Xg[idx];
        }
        __syncthreads();
        #pragma unroll 8
        for (int kk = 0; kk < 32; ++kk) {
            float4 a0 = *reinterpret_cast<const float4*>(Wt + kk*WPITCH + ty*4);
            float4 a1 = *reinterpret_cast<const float4*>(Wt + kk*WPITCH + 64 + ty*4);
            float4 b0 = *reinterpret_cast<const float4*>(Xt + kk*128 + tx*4);
            float4 b1 = *reinterpret_cast<const float4*>(Xt + kk*128 + 64 + tx*4);
            float a[8] = {a0.x,a0.y,a0.z,a0.w,a1.x,a1.y,a1.z,a1.w};
            float b[8] = {b0.x,b0.y,b0.z,b0.w,b1.x,b1.y,b1.z,b1.w};
            #pragma unroll
            for (int i = 0; i < 8; ++i)
                #pragma unroll
                for (int j = 0; j < 8; ++j)
                    acc[i][j] += a[i] * b[j];
        }
        __syncthreads();
    }
    #pragma unroll
    for (int i = 0; i < 8; ++i) {
        int r = (i < 4) ? (ty*4 + i) : (64 + ty*4 + (i - 4));
        #pragma unroll
        for (int j = 0; j < 8; ++j) {
            int c = (j < 4) ? (tx*4 + j) : (64 + tx*4 + (j - 4));
            C[r * 128 + c] = acc[i][j];
        }
    }
    __syncthreads();
}

__global__ __launch_bounds__(256, 1)
void attend_kernel(const float* __restrict__ X, const float* __restrict__ Wa,
                   const float* __restrict__ va)
{
    extern __shared__ float sm[];
    float* Aq   = sm + S_AQ;
    float* Ap   = sm + S_AP;
    float* Wt   = sm + S_WT;
    float* Xt   = sm + S_XT;
    float* vas  = sm + S_VA;
    float* beta = sm + S_BETA;
    float* red  = sm + S_RED;

    const int m   = blockIdx.x;
    const int tid = threadIdx.x;
    const int tx = tid & 15, ty = tid >> 4;
    const int lane = tid & 31, warp = tid >> 5;
    const size_t xm = (size_t)m * XROW * NDIM;

    if (tid < 128) vas[tid] = va[tid];

    // shared Xq contribution: Aq = Wa[:, :768] @ Xq
    gemm_128x128(Aq, Wt, Xt, Wa, X, 0, xm, tid, tx, ty);

    for (int part = 0; part < 2; ++part) {
        const int xe   = (part == 0) ? EMB : (2*EMB + 1);
        const int vrow = (part == 0) ? (2*EMB) : (3*EMB + 1);

        // Ap = Wa[:, 768:] @ Xp
        gemm_128x128(Ap, Wt, Xt, Wa, X, EMB, xm + (size_t)xe * NDIM, tid, tx, ty);

        // score[n] = valid[n] * sum_k va[k] * tanh(Aq[k][n] + Ap[k][n]), then softmax
        float s = -INFINITY;
        if (tid < 128) {
            const int n = tid;
            float sc = 0.f;
            #pragma unroll 4
            for (int k = 0; k < 128; ++k)
                sc += vas[k] * tanhf(Aq[k*128 + n] + Ap[k*128 + n]);
            s = sc * X[xm + (size_t)vrow * NDIM + n];
        }
        float v = s;
        #pragma unroll
        for (int off = 16; off; off >>= 1)
            v = fmaxf(v, __shfl_xor_sync(0xffffffffu, v, off));
        if (lane == 0) red[warp] = v;
        __syncthreads();
        float mx = red[0];
        #pragma unroll
        for (int w = 1; w < 8; ++w) mx = fmaxf(mx, red[w]);
        float ex = (tid < 128) ? expf(s - mx) : 0.f;
        v = ex;
        #pragma unroll
        for (int off = 16; off; off >>= 1)
            v += __shfl_xor_sync(0xffffffffu, v, off);
        __syncthreads();                 // red max-phase fully read
        if (lane == 0) red[warp] = v;
        __syncthreads();
        float sum = 0.f;
        #pragma unroll
        for (int w = 0; w < 8; ++w) sum += red[w];
        if (tid < 128) beta[tid] = ex / sum;
        __syncthreads();

        // pooling: p[e] = sum_n beta[n] * Xp[m, e, n]  (warp per e-row, coalesced)
        float* dst = g_P + (size_t)part * (MROWS * EMB) + (size_t)m * EMB;
        for (int e = warp; e < EMB; e += 8) {
            const float* row = X + xm + (size_t)(xe + e) * NDIM;
            float a = beta[lane]      * row[lane]
                    + beta[lane + 32] * row[lane + 32]
                    + beta[lane + 64] * row[lane + 64]
                    + beta[lane + 96] * row[lane + 96];
            #pragma unroll
            for (int off = 16; off; off >>= 1)
                a += __shfl_xor_sync(0xffffffffu, a, off);
            if (lane == 0) dst[e] = a;
        }
        __syncthreads();
    }

    // qv = Xq[m, :, 0]
    float* dq = g_P + (size_t)2 * (MROWS * EMB) + (size_t)m * EMB;
    for (int e = tid; e < EMB; e += 256)
        dq[e] = X[xm + (size_t)e * NDIM];
}

// C = A @ B^T + bias, optional relu.  stage 0: g_P@W1^T -> g_H ; stage 1: relu(g_H@W2^T) -> g_Z
__global__ __launch_bounds__(256)
void mlp_gemm(int stage, const float* __restrict__ B, const float* __restrict__ bias)
{
    __shared__ __align__(16) float At[32 * WPITCH];
    __shared__ __align__(16) float Bt[32 * WPITCH];
    const float* __restrict__ A = (stage == 0) ? g_P : g_H;
    float* __restrict__ C       = (stage == 0) ? g_H : g_Z;

    const int tid = threadIdx.x;
    const int tx = tid & 15, ty = tid >> 4;
    const int i0 = blockIdx.x * 128, j0 = blockIdx.y * 128;

    float acc[8][8];
    #pragma unroll
    for (int i = 0; i < 8; ++i)
        #pragma unroll
        for (int j = 0; j < 8; ++j) acc[i][j] = 0.f;

    for (int k0 = 0; k0 < EMB; k0 += 32) {
        #pragma unroll
        for (int l = 0; l < 16; ++l) {
            int idx = tid + l * 256;
            int r = idx >> 5, kk = idx & 31;
            At[kk * WPITCH + r] = A[(size_t)(i0 + r) * EMB + k0 + kk];
            Bt[kk * WPITCH + r] = B[(size_t)(j0 + r) * EMB + k0 + kk];
        }
        __syncthreads();
        #pragma unroll 8
        for (int kk = 0; kk < 32; ++kk) {
            float4 a0 = *reinterpret_cast<const float4*>(At + kk*WPITCH + ty*4);
            float4 a1 = *reinterpret_cast<const float4*>(At + kk*WPITCH + 64 + ty*4);
            float4 b0 = *reinterpret_cast<const float4*>(Bt + kk*WPITCH + tx*4);
            float4 b1 = *reinterpret_cast<const float4*>(Bt + kk*WPITCH + 64 + tx*4);
            float a[8] = {a0.x,a0.y,a0.z,a0.w,a1.x,a1.y,a1.z,a1.w};
            float b[8] = {b0.x,b0.y,b0.z,b0.w,b1.x,b1.y,b1.z,b1.w};
            #pragma unroll
            for (int i = 0; i < 8; ++i)
                #pragma unroll
                for (int j = 0; j < 8; ++j)
                    acc[i][j] += a[i] * b[j];
        }
        __syncthreads();
    }
    #pragma unroll
    for (int i = 0; i < 8; ++i) {
        int r = i0 + ((i < 4) ? (ty*4 + i) : (64 + ty*4 + (i - 4)));
        #pragma unroll
        for (int j = 0; j < 8; ++j) {
            int cc = (j < 4) ? (tx*4 + j) : (64 + tx*4 + (j - 4));
            int c = j0 + cc;
            float vv = acc[i][j] + bias[c];
            if (stage == 1) vv = fmaxf(vv, 0.f);
            C[(size_t)r * EMB + c] = vv;
        }
    }
}

__global__ void combine_kernel(const float* __restrict__ W3, const float* __restrict__ b3,
                               float* __restrict__ out)
{
    __shared__ float red[4];
    const int m = blockIdx.x, tid = threadIdx.x;
    const float* z1 = g_Z + (size_t)m * EMB;
    const float* z2 = g_Z + (size_t)(MROWS + m) * EMB;
    const float* zq = g_Z + (size_t)(2*MROWS + m) * EMB;
    float acc = 0.f;
    for (int e = tid; e < EMB; e += 128) {
        float a = z1[e], b = z2[e], c = zq[e];
        acc += W3[e] * a + W3[EMB + e] * b
             + W3[2*EMB + e] * fabsf(a - b)
             + W3[3*EMB + e] * fabsf(a - c)
             + W3[4*EMB + e] * fabsf(b - c);
    }
    #pragma unroll
    for (int off = 16; off; off >>= 1)
        acc += __shfl_xor_sync(0xffffffffu, acc, off);
    const int lane = tid & 31, warp = tid >> 5;
    if (lane == 0) red[warp] = acc;
    __syncthreads();
    if (tid == 0)
        out[m] = fmaxf(red[0] + red[1] + red[2] + red[3] + b3[0], 0.f);
}

extern "C" void kernel_launch(void* const* d_in, const int* in_sizes, int n_in,
                              void* d_out, int out_size)
{
    const float* X  = (const float*)d_in[0];
    const float* Wa = (const float*)d_in[1];
    const float* va = (const float*)d_in[2];
    const float* W1 = (const float*)d_in[3];
    const float* b1 = (const float*)d_in[4];
    const float* W2 = (const float*)d_in[5];
    const float* b2 = (const float*)d_in[6];
    const float* W3 = (const float*)d_in[7];
    const float* b3 = (const float*)d_in[8];
    float* out = (float*)d_out;

    cudaFuncSetAttribute(attend_kernel, cudaFuncAttributeMaxDynamicSharedMemorySize, SMEM_BYTES);
    attend_kernel<<<MROWS, 256, SMEM_BYTES>>>(X, Wa, va);

    dim3 g((3 * MROWS) / 128, EMB / 128);
    mlp_gemm<<<g, 256>>>(0, W1, b1);
    mlp_gemm<<<g, 256>>>(1, W2, b2);
    combine_kernel<<<MROWS, 128>>>(W3, b3, out);
}

// round 5
// speedup vs baseline: 2.6716x; 2.6716x over previous
#include <cuda_runtime.h>
#include <cuda_bf16.h>
#include <math.h>
#include <stdint.h>

#define EMB   768
#define NDIM  128
#define MROWS 1024
#define XROW  (3*EMB + 2)   // 2306
#define WPITCH 132

// ---------------- global scratch (no allocations) ----------------
__device__ float g_P[3 * MROWS * EMB];
__device__ float g_H[3 * MROWS * EMB];
__device__ float g_Z[3 * MROWS * EMB];
__device__ __align__(16) __nv_bfloat16 g_WaB[NDIM * 2 * EMB];   // Wa as bf16, same layout

#define APITCH 72    // bf16 per A-tile row (144B, 16B-aligned, conflict-free ldmatrix)
#define BPITCH 136   // bf16 per B-tile row (272B, 16B-aligned, conflict-free ldmatrix.trans)

// ---------------- helpers ----------------
__device__ __forceinline__ uint32_t smem_u32(const void* p) {
    uint32_t a;
    asm("{ .reg .u64 t; cvta.to.shared.u64 t, %1; cvt.u32.u64 %0, t; }" : "=r"(a) : "l"(p));
    return a;
}
__device__ __forceinline__ void ldsm4(uint32_t& r0, uint32_t& r1, uint32_t& r2, uint32_t& r3, uint32_t addr) {
    asm volatile("ldmatrix.sync.aligned.m8n8.x4.shared.b16 {%0,%1,%2,%3}, [%4];"
                 : "=r"(r0), "=r"(r1), "=r"(r2), "=r"(r3) : "r"(addr));
}
__device__ __forceinline__ void ldsm4t(uint32_t& r0, uint32_t& r1, uint32_t& r2, uint32_t& r3, uint32_t addr) {
    asm volatile("ldmatrix.sync.aligned.m8n8.x4.trans.shared.b16 {%0,%1,%2,%3}, [%4];"
                 : "=r"(r0), "=r"(r1), "=r"(r2), "=r"(r3) : "r"(addr));
}
__device__ __forceinline__ void mma16816(float* d, const uint32_t* a, uint32_t b0, uint32_t b1) {
    asm volatile("mma.sync.aligned.m16n8k16.row.col.f32.bf16.bf16.f32 "
                 "{%0,%1,%2,%3}, {%4,%5,%6,%7}, {%8,%9}, {%0,%1,%2,%3};"
                 : "+f"(d[0]), "+f"(d[1]), "+f"(d[2]), "+f"(d[3])
                 : "r"(a[0]), "r"(a[1]), "r"(a[2]), "r"(a[3]), "r"(b0), "r"(b1));
}

// ---------------- Wa prep: fp32 -> bf16, same layout ----------------
__global__ void prep_wa(const float* __restrict__ Wa) {
    int idx = blockIdx.x * blockDim.x + threadIdx.x;   // 0 .. 196607
    g_WaB[idx] = __float2bfloat16(Wa[idx]);
}

// ---------------- attend: bf16 mma.sync, fused score/softmax/pool ----------------
__global__ __launch_bounds__(256, 2)
void attend_mma(const float* __restrict__ X, const float* __restrict__ va)
{
    __shared__ __align__(16) __nv_bfloat16 As[128 * APITCH];   // 18432 B
    __shared__ __align__(16) __nv_bfloat16 Bs[64 * BPITCH];    // 17408 B
    __shared__ float vas[128];
    __shared__ float spart[2][128];
    __shared__ float beta[128];
    __shared__ float red[8];

    const int tid  = threadIdx.x, lane = tid & 31, warp = tid >> 5;
    const int m    = blockIdx.x;
    const size_t xm = (size_t)m * XROW * NDIM;
    const int wm = warp & 1, wn = warp >> 1;      // warp tile: rows 64*wm, cols 32*wn
    const int m0 = wm * 64, n0 = wn * 32;

    if (tid < 128) vas[tid] = va[tid];

    const uint32_t As32 = smem_u32(As), Bs32 = smem_u32(Bs);
    // per-lane ldmatrix base addresses
    const uint32_t aAddr = As32 + (uint32_t)(m0 + (lane & 7) + 8 * ((lane >> 3) & 1)) * 144u
                                + (uint32_t)(lane >> 4) * 16u;
    const uint32_t bAddr = Bs32 + (uint32_t)(lane & 15) * 272u
                                + (uint32_t)(n0 + 8 * (lane >> 4)) * 2u;

    // B-tile copy indexing: thread -> (n pair, e group)
    const int n2 = tid & 63, eg4 = tid >> 6;

    for (int part = 0; part < 2; ++part) {
        const int xp = (part == 0) ? EMB : (2 * EMB + 1);

        float d[4][4][4];
        #pragma unroll
        for (int mt = 0; mt < 4; ++mt)
            #pragma unroll
            for (int nt = 0; nt < 4; ++nt)
                #pragma unroll
                for (int q = 0; q < 4; ++q) d[mt][nt][q] = 0.f;

        for (int c = 0; c < 24; ++c) {          // K = 1536 in chunks of 64
            const int eg = c * 64;
            // ---- A tile: g_WaB rows 0..127, cols eg..eg+63 -> As[128][72]
            {
                const int4* asrc = reinterpret_cast<const int4*>(g_WaB);
                int4* adst = reinterpret_cast<int4*>(As);
                const int csrc = eg >> 3;       // int4 units per row = 192
                #pragma unroll
                for (int l4 = 0; l4 < 4; ++l4) {
                    int idx = tid + 256 * l4;   // 0..1023
                    int r = idx >> 3, u = idx & 7;
                    adst[r * 9 + u] = asrc[r * 192 + csrc + u];
                }
            }
            // ---- B tile: X rows srow..srow+63 (fp32) -> bf16 Bs[64][136]
            {
                const int srow = (c < 12) ? eg : (xp + eg - EMB);
                const float2* bsrc = reinterpret_cast<const float2*>(X + xm + (size_t)srow * NDIM);
                #pragma unroll
                for (int i = 0; i < 16; ++i) {
                    int e = eg4 * 16 + i;
                    float2 f = bsrc[e * 64 + n2];
                    __nv_bfloat162 h = __floats2bfloat162_rn(f.x, f.y);
                    *reinterpret_cast<uint32_t*>(
                        reinterpret_cast<char*>(Bs) + e * 272 + n2 * 4) =
                        *reinterpret_cast<uint32_t*>(&h);
                }
            }
            __syncthreads();
            // ---- MMA: 4 k-steps of 16
            #pragma unroll
            for (int ks = 0; ks < 4; ++ks) {
                uint32_t bl[2][4];
                #pragma unroll
                for (int h = 0; h < 2; ++h)
                    ldsm4t(bl[h][0], bl[h][1], bl[h][2], bl[h][3],
                           bAddr + (uint32_t)ks * (16u * 272u) + (uint32_t)h * 32u);
                #pragma unroll
                for (int mt = 0; mt < 4; ++mt) {
                    uint32_t a[4];
                    ldsm4(a[0], a[1], a[2], a[3],
                          aAddr + (uint32_t)mt * (16u * 144u) + (uint32_t)ks * 32u);
                    #pragma unroll
                    for (int nt = 0; nt < 4; ++nt)
                        mma16816(d[mt][nt], a, bl[nt >> 1][(nt & 1) * 2], bl[nt >> 1][(nt & 1) * 2 + 1]);
                }
            }
            __syncthreads();
        }

        // ---- score: s[n] = sum_k va[k]*tanh(D[k][n]), reduced from fragments
        float va8[8];
        #pragma unroll
        for (int mt = 0; mt < 4; ++mt)
            #pragma unroll
            for (int h = 0; h < 2; ++h)
                va8[mt * 2 + h] = vas[m0 + (lane >> 2) + 16 * mt + 8 * h];
        #pragma unroll
        for (int nt = 0; nt < 4; ++nt) {
            #pragma unroll
            for (int j = 0; j < 2; ++j) {
                float s = 0.f;
                #pragma unroll
                for (int mt = 0; mt < 4; ++mt)
                    #pragma unroll
                    for (int h = 0; h < 2; ++h) {
                        float th;
                        asm("tanh.approx.f32 %0, %1;" : "=f"(th) : "f"(d[mt][nt][2 * h + j]));
                        s += va8[mt * 2 + h] * th;
                    }
                s += __shfl_xor_sync(0xffffffffu, s, 4);
                s += __shfl_xor_sync(0xffffffffu, s, 8);
                s += __shfl_xor_sync(0xffffffffu, s, 16);
                if (lane < 4) spart[wm][n0 + 8 * nt + 2 * lane + j] = s;
            }
        }
        __syncthreads();

        // ---- softmax over n (threads 0..127)
        const int vrow = (part == 0) ? (2 * EMB) : (3 * EMB + 1);
        float s = -INFINITY;
        if (tid < 128)
            s = (spart[0][tid] + spart[1][tid]) * X[xm + (size_t)vrow * NDIM + tid];
        float v = s;
        #pragma unroll
        for (int o = 16; o; o >>= 1) v = fmaxf(v, __shfl_xor_sync(0xffffffffu, v, o));
        if (lane == 0) red[warp] = v;
        __syncthreads();
        float mx = red[0];
        #pragma unroll
        for (int w = 1; w < 8; ++w) mx = fmaxf(mx, red[w]);
        float ex = (tid < 128) ? expf(s - mx) : 0.f;
        v = ex;
        #pragma unroll
        for (int o = 16; o; o >>= 1) v += __shfl_xor_sync(0xffffffffu, v, o);
        __syncthreads();
        if (lane == 0) red[warp] = v;
        __syncthreads();
        float sum = 0.f;
        #pragma unroll
        for (int w = 0; w < 8; ++w) sum += red[w];
        if (tid < 128) beta[tid] = ex / sum;
        __syncthreads();

        // ---- pool: p[e] = sum_n beta[n] * Xp[e][n]
        float* dst = g_P + (size_t)part * (MROWS * EMB) + (size_t)m * EMB;
        for (int e = warp; e < EMB; e += 8) {
            const float* row = X + xm + (size_t)(xp + e) * NDIM;
            float a = beta[lane]      * row[lane]
                    + beta[lane + 32] * row[lane + 32]
                    + beta[lane + 64] * row[lane + 64]
                    + beta[lane + 96] * row[lane + 96];
            #pragma unroll
            for (int o = 16; o; o >>= 1) a += __shfl_xor_sync(0xffffffffu, a, o);
            if (lane == 0) dst[e] = a;
        }
        __syncthreads();
    }

    // qv = Xq[m, :, 0]
    float* dq = g_P + (size_t)(2 * MROWS + m) * EMB;
    for (int e = tid; e < EMB; e += 256)
        dq[e] = X[xm + (size_t)e * NDIM];
}

// ---------------- MLP (fp32 SIMT, proven) ----------------
__global__ __launch_bounds__(256)
void mlp_gemm(int stage, const float* __restrict__ B, const float* __restrict__ bias)
{
    __shared__ __align__(16) float At[32 * WPITCH];
    __shared__ __align__(16) float Bt[32 * WPITCH];
    const float* __restrict__ A = (stage == 0) ? g_P : g_H;
    float* __restrict__ C       = (stage == 0) ? g_H : g_Z;

    const int tid = threadIdx.x;
    const int tx = tid & 15, ty = tid >> 4;
    const int i0 = blockIdx.x * 128, j0 = blockIdx.y * 128;

    float acc[8][8];
    #pragma unroll
    for (int i = 0; i < 8; ++i)
        #pragma unroll
        for (int j = 0; j < 8; ++j) acc[i][j] = 0.f;

    for (int k0 = 0; k0 < EMB; k0 += 32) {
        #pragma unroll
        for (int l = 0; l < 16; ++l) {
            int idx = tid + l * 256;
            int r = idx >> 5, kk = idx & 31;
            At[kk * WPITCH + r] = A[(size_t)(i0 + r) * EMB + k0 + kk];
            Bt[kk * WPITCH + r] = B[(size_t)(j0 + r) * EMB + k0 + kk];
        }
        __syncthreads();
        #pragma unroll 8
        for (int kk = 0; kk < 32; ++kk) {
            float4 a0 = *reinterpret_cast<const float4*>(At + kk*WPITCH + ty*4);
            float4 a1 = *reinterpret_cast<const float4*>(At + kk*WPITCH + 64 + ty*4);
            float4 b0 = *reinterpret_cast<const float4*>(Bt + kk*WPITCH + tx*4);
            float4 b1 = *reinterpret_cast<const float4*>(Bt + kk*WPITCH + 64 + tx*4);
            float a[8] = {a0.x,a0.y,a0.z,a0.w,a1.x,a1.y,a1.z,a1.w};
            float b[8] = {b0.x,b0.y,b0.z,b0.w,b1.x,b1.y,b1.z,b1.w};
            #pragma unroll
            for (int i = 0; i < 8; ++i)
                #pragma unroll
                for (int j = 0; j < 8; ++j)
                    acc[i][j] += a[i] * b[j];
        }
        __syncthreads();
    }
    #pragma unroll
    for (int i = 0; i < 8; ++i) {
        int r = i0 + ((i < 4) ? (ty*4 + i) : (64 + ty*4 + (i - 4)));
        #pragma unroll
        for (int j = 0; j < 8; ++j) {
            int cc = (j < 4) ? (tx*4 + j) : (64 + tx*4 + (j - 4));
            int c = j0 + cc;
            float vv = acc[i][j] + bias[c];
            if (stage == 1) vv = fmaxf(vv, 0.f);
            C[(size_t)r * EMB + c] = vv;
        }
    }
}

__global__ void combine_kernel(const float* __restrict__ W3, const float* __restrict__ b3,
                               float* __restrict__ out)
{
    __shared__ float red[4];
    const int m = blockIdx.x, tid = threadIdx.x;
    const float* z1 = g_Z + (size_t)m * EMB;
    const float* z2 = g_Z + (size_t)(MROWS + m) * EMB;
    const float* zq = g_Z + (size_t)(2*MROWS + m) * EMB;
    float acc = 0.f;
    for (int e = tid; e < EMB; e += 128) {
        float a = z1[e], b = z2[e], c = zq[e];
        acc += W3[e] * a + W3[EMB + e] * b
             + W3[2*EMB + e] * fabsf(a - b)
             + W3[3*EMB + e] * fabsf(a - c)
             + W3[4*EMB + e] * fabsf(b - c);
    }
    #pragma unroll
    for (int off = 16; off; off >>= 1)
        acc += __shfl_xor_sync(0xffffffffu, acc, off);
    const int lane = tid & 31, warp = tid >> 5;
    if (lane == 0) red[warp] = acc;
    __syncthreads();
    if (tid == 0)
        out[m] = fmaxf(red[0] + red[1] + red[2] + red[3] + b3[0], 0.f);
}

extern "C" void kernel_launch(void* const* d_in, const int* in_sizes, int n_in,
                              void* d_out, int out_size)
{
    const float* X  = (const float*)d_in[0];
    const float* Wa = (const float*)d_in[1];
    const float* va = (const float*)d_in[2];
    const float* W1 = (const float*)d_in[3];
    const float* b1 = (const float*)d_in[4];
    const float* W2 = (const float*)d_in[5];
    const float* b2 = (const float*)d_in[6];
    const float* W3 = (const float*)d_in[7];
    const float* b3 = (const float*)d_in[8];
    float* out = (float*)d_out;

    prep_wa<<<768, 256>>>(Wa);
    attend_mma<<<MROWS, 256>>>(X, va);

    dim3 g((3 * MROWS) / 128, EMB / 128);
    mlp_gemm<<<g, 256>>>(0, W1, b1);
    mlp_gemm<<<g, 256>>>(1, W2, b2);
    combine_kernel<<<MROWS, 128>>>(W3, b3, out);
}

// round 8
// speedup vs baseline: 3.1601x; 1.1829x over previous
#include <cuda_runtime.h>
#include <cuda_bf16.h>
#include <math.h>
#include <stdint.h>

#define EMB   768
#define NDIM  128
#define MROWS 1024
#define XROW  (3*EMB + 2)   // 2306
#define WPITCH 132

// ---------------- global scratch (no allocations) ----------------
__device__ float g_P[3 * MROWS * EMB];
__device__ float g_HA[3 * MROWS * EMB];
__device__ float g_HB[3 * MROWS * EMB];
__device__ float g_ZA[3 * MROWS * EMB];
__device__ float g_ZB[3 * MROWS * EMB];
__device__ __align__(16) __nv_bfloat16 g_WaB[NDIM * 2 * EMB];   // Wa as bf16
__device__ __align__(16) float4 g_Dq[(size_t)MROWS * 16 * 256]; // Dq snapshot (67MB)

// ---------------- attend dynamic smem offsets (bytes) ----------------
#define AS0   0
#define AS1   18432
#define BS0   36864
#define BS1   54272
#define SVAS  71680
#define SPART 72192
#define SBETA 73216
#define SRED  73728
#define SMT   73760

// ---------------- helpers ----------------
__device__ __forceinline__ uint32_t smem_u32(const void* p) {
    uint32_t a;
    asm("{ .reg .u64 t; cvta.to.shared.u64 t, %1; cvt.u32.u64 %0, t; }" : "=r"(a) : "l"(p));
    return a;
}
__device__ __forceinline__ void ldsm4(uint32_t& r0, uint32_t& r1, uint32_t& r2, uint32_t& r3, uint32_t addr) {
    asm volatile("ldmatrix.sync.aligned.m8n8.x4.shared.b16 {%0,%1,%2,%3}, [%4];"
                 : "=r"(r0), "=r"(r1), "=r"(r2), "=r"(r3) : "r"(addr));
}
__device__ __forceinline__ void ldsm4t(uint32_t& r0, uint32_t& r1, uint32_t& r2, uint32_t& r3, uint32_t addr) {
    asm volatile("ldmatrix.sync.aligned.m8n8.x4.trans.shared.b16 {%0,%1,%2,%3}, [%4];"
                 : "=r"(r0), "=r"(r1), "=r"(r2), "=r"(r3) : "r"(addr));
}
__device__ __forceinline__ void mma16816(float* d, const uint32_t* a, uint32_t b0, uint32_t b1) {
    asm volatile("mma.sync.aligned.m16n8k16.row.col.f32.bf16.bf16.f32 "
                 "{%0,%1,%2,%3}, {%4,%5,%6,%7}, {%8,%9}, {%0,%1,%2,%3};"
                 : "+f"(d[0]), "+f"(d[1]), "+f"(d[2]), "+f"(d[3])
                 : "r"(a[0]), "r"(a[1]), "r"(a[2]), "r"(a[3]), "r"(b0), "r"(b1));
}
__device__ __forceinline__ void cpasync16(uint32_t dst, const void* src) {
    asm volatile("cp.async.cg.shared.global [%0], [%1], 16;" :: "r"(dst), "l"(src));
}
__device__ __forceinline__ void cp_commit() { asm volatile("cp.async.commit_group;"); }
__device__ __forceinline__ void cp_wait0()  { asm volatile("cp.async.wait_group 0;" ::: "memory"); }

// ---------------- Wa prep ----------------
__global__ void prep_wa(const float* __restrict__ Wa) {
    int idx = blockIdx.x * blockDim.x + threadIdx.x;
    g_WaB[idx] = __float2bfloat16(Wa[idx]);
}

// ---------------- attend: pipelined bf16 mma.sync ----------------
__global__ __launch_bounds__(256, 2)
void attend_mma(const float* __restrict__ X, const float* __restrict__ va)
{
    extern __shared__ char smc[];
    const uint32_t smb = smem_u32(smc);
    float* vas   = (float*)(smc + SVAS);
    float* spart = (float*)(smc + SPART);   // [2][128]
    float* beta  = (float*)(smc + SBETA);
    float* red   = (float*)(smc + SRED);

    const int tid  = threadIdx.x, lane = tid & 31, warp = tid >> 5;
    const int m    = blockIdx.x;
    const size_t xm = (size_t)m * XROW * NDIM;
    const int wm = warp & 1, wn = warp >> 1;
    const int m0 = wm * 64, n0 = wn * 32;

    if (tid < 128) vas[tid] = va[tid];

    // lane-constant pieces of ldmatrix addresses
    const uint32_t aLane = (uint32_t)(m0 + (lane & 7) + 8 * ((lane >> 3) & 1)) * 144u
                         + (uint32_t)(lane >> 4) * 16u;
    const uint32_t bLane = (uint32_t)(lane & 15) * 272u + (uint32_t)(n0 + 8 * (lane >> 4)) * 2u;

    // A-copy per-thread src/dst offsets (64B per thread)
    const int ar = tid >> 1, ah = tid & 1;
    // B-copy indexing
    const int n2 = tid & 63, eg4 = tid >> 6;

    #pragma unroll
    for (int part = 0; part < 2; ++part) {
        const int nch = part ? 12 : 24;
        const int xp  = part ? (2 * EMB + 1) : EMB;

        float d[4][4][4];
        if (part == 0) {
            #pragma unroll
            for (int mt = 0; mt < 4; ++mt)
                #pragma unroll
                for (int nt = 0; nt < 4; ++nt)
                    #pragma unroll
                    for (int q = 0; q < 4; ++q) d[mt][nt][q] = 0.f;
        } else {
            const float4* src = g_Dq + (size_t)m * 16 * 256 + tid;
            #pragma unroll
            for (int i = 0; i < 16; ++i) {
                float4 v = src[(size_t)i * 256];
                d[i >> 2][i & 3][0] = v.x; d[i >> 2][i & 3][1] = v.y;
                d[i >> 2][i & 3][2] = v.z; d[i >> 2][i & 3][3] = v.w;
            }
        }

        // ---- prologue: chunk 0 into buf 0
        {
            const int colblk = part ? 12 : 0;
            const int srow   = part ? xp : 0;
            const __nv_bfloat16* asrc = g_WaB + ar * (2 * EMB) + colblk * 64 + ah * 32;
            const uint32_t adst = smb + AS0 + (uint32_t)ar * 144u + (uint32_t)ah * 64u;
            #pragma unroll
            for (int i = 0; i < 4; ++i) cpasync16(adst + i * 16, (const char*)asrc + i * 16);
            cp_commit();
            const float2* bsrc = (const float2*)(X + xm + (size_t)srow * NDIM);
            #pragma unroll
            for (int i = 0; i < 16; ++i) {
                const int e = eg4 * 16 + i;
                float2 f = bsrc[e * 64 + n2];
                __nv_bfloat162 h = __floats2bfloat162_rn(f.x, f.y);
                *(uint32_t*)(smc + BS0 + e * 272 + n2 * 4) = *(uint32_t*)&h;
            }
            cp_wait0();
            __syncthreads();
        }

        for (int c = 0; c < nch; ++c) {
            const int buf = c & 1;
            float2 b2[16];
            if (c + 1 < nch) {
                const int cc = c + 1;
                const int colblk = part ? (12 + cc) : cc;
                const int srow   = part ? (xp + cc * 64)
                                        : ((cc < 12) ? cc * 64 : (EMB + (cc - 12) * 64));
                // A -> other buffer via cp.async (overlaps MMA)
                const __nv_bfloat16* asrc = g_WaB + ar * (2 * EMB) + colblk * 64 + ah * 32;
                const uint32_t adst = smb + (buf ? AS0 : AS1) + (uint32_t)ar * 144u + (uint32_t)ah * 64u;
                #pragma unroll
                for (int i = 0; i < 4; ++i) cpasync16(adst + i * 16, (const char*)asrc + i * 16);
                cp_commit();
                // B -> regs
                const float2* bsrc = (const float2*)(X + xm + (size_t)srow * NDIM);
                #pragma unroll
                for (int i = 0; i < 16; ++i)
                    b2[i] = bsrc[(eg4 * 16 + i) * 64 + n2];
            }

            // ---- MMA on buf
            const uint32_t aAddr = smb + (buf ? AS1 : AS0) + aLane;
            const uint32_t bAddr = smb + (buf ? BS1 : BS0) + bLane;
            #pragma unroll
            for (int ks = 0; ks < 4; ++ks) {
                uint32_t bl[2][4];
                #pragma unroll
                for (int h = 0; h < 2; ++h)
                    ldsm4t(bl[h][0], bl[h][1], bl[h][2], bl[h][3],
                           bAddr + (uint32_t)ks * (16u * 272u) + (uint32_t)h * 32u);
                #pragma unroll
                for (int mt = 0; mt < 4; ++mt) {
                    uint32_t a[4];
                    ldsm4(a[0], a[1], a[2], a[3],
                          aAddr + (uint32_t)mt * (16u * 144u) + (uint32_t)ks * 32u);
                    #pragma unroll
                    for (int nt = 0; nt < 4; ++nt)
                        mma16816(d[mt][nt], a, bl[nt >> 1][(nt & 1) * 2], bl[nt >> 1][(nt & 1) * 2 + 1]);
                }
            }

            // snapshot Dq after q-half of part 0
            if (part == 0 && c == 11) {
                float4* dst = g_Dq + (size_t)m * 16 * 256 + tid;
                #pragma unroll
                for (int i = 0; i < 16; ++i)
                    dst[(size_t)i * 256] = make_float4(d[i >> 2][i & 3][0], d[i >> 2][i & 3][1],
                                                       d[i >> 2][i & 3][2], d[i >> 2][i & 3][3]);
            }

            if (c + 1 < nch) {
                char* bb = smc + (buf ? BS0 : BS1);
                #pragma unroll
                for (int i = 0; i < 16; ++i) {
                    const int e = eg4 * 16 + i;
                    __nv_bfloat162 h = __floats2bfloat162_rn(b2[i].x, b2[i].y);
                    *(uint32_t*)(bb + e * 272 + n2 * 4) = *(uint32_t*)&h;
                }
            }
            cp_wait0();
            __syncthreads();
        }

        // ---- score: s[n] = sum_k va[k]*tanh(D[k][n])
        float va8[8];
        #pragma unroll
        for (int mt = 0; mt < 4; ++mt)
            #pragma unroll
            for (int h = 0; h < 2; ++h)
                va8[mt * 2 + h] = vas[m0 + (lane >> 2) + 16 * mt + 8 * h];
        #pragma unroll
        for (int nt = 0; nt < 4; ++nt) {
            #pragma unroll
            for (int j = 0; j < 2; ++j) {
                float s = 0.f;
                #pragma unroll
                for (int mt = 0; mt < 4; ++mt)
                    #pragma unroll
                    for (int h = 0; h < 2; ++h) {
                        float th;
                        asm("tanh.approx.f32 %0, %1;" : "=f"(th) : "f"(d[mt][nt][2 * h + j]));
                        s += va8[mt * 2 + h] * th;
                    }
                s += __shfl_xor_sync(0xffffffffu, s, 4);
                s += __shfl_xor_sync(0xffffffffu, s, 8);
                s += __shfl_xor_sync(0xffffffffu, s, 16);
                if (lane < 4) spart[wm * 128 + n0 + 8 * nt + 2 * lane + j] = s;
            }
        }
        __syncthreads();

        // ---- softmax over n
        const int vrow = part ? (3 * EMB + 1) : (2 * EMB);
        float s = -INFINITY;
        if (tid < 128)
            s = (spart[tid] + spart[128 + tid]) * X[xm + (size_t)vrow * NDIM + tid];
        float v = s;
        #pragma unroll
        for (int o = 16; o; o >>= 1) v = fmaxf(v, __shfl_xor_sync(0xffffffffu, v, o));
        if (lane == 0) red[warp] = v;
        __syncthreads();
        float mx = red[0];
        #pragma unroll
        for (int w = 1; w < 8; ++w) mx = fmaxf(mx, red[w]);
        float ex = (tid < 128) ? expf(s - mx) : 0.f;
        v = ex;
        #pragma unroll
        for (int o = 16; o; o >>= 1) v += __shfl_xor_sync(0xffffffffu, v, o);
        __syncthreads();
        if (lane == 0) red[warp] = v;
        __syncthreads();
        float sum = 0.f;
        #pragma unroll
        for (int w = 0; w < 8; ++w) sum += red[w];
        if (tid < 128) beta[tid] = ex / sum;
        __syncthreads();

        // ---- pool
        float* dst = g_P + (size_t)part * (MROWS * EMB) + (size_t)m * EMB;
        for (int e = warp; e < EMB; e += 8) {
            const float* row = X + xm + (size_t)(xp + e) * NDIM;
            float a = beta[lane]      * row[lane]
                    + beta[lane + 32] * row[lane + 32]
                    + beta[lane + 64] * row[lane + 64]
                    + beta[lane + 96] * row[lane + 96];
            #pragma unroll
            for (int o = 16; o; o >>= 1) a += __shfl_xor_sync(0xffffffffu, a, o);
            if (lane == 0) dst[e] = a;
        }
        __syncthreads();
    }

    // qv = Xq[m, :, 0]
    float* dq = g_P + (size_t)(2 * MROWS + m) * EMB;
    for (int e = tid; e < EMB; e += 256)
        dq[e] = X[xm + (size_t)e * NDIM];
}

// ---------------- MLP split-K (fp32 SIMT), grid (24,6,2) ----------------
__global__ __launch_bounds__(256, 2)
void mlp_gemm(int stage, const float* __restrict__ B, const float* __restrict__ bias)
{
    __shared__ __align__(16) float At[32 * WPITCH];
    __shared__ __align__(16) float Bt[32 * WPITCH];

    const int ks = blockIdx.z;
    float* __restrict__ C = (stage == 0) ? (ks ? g_HB : g_HA) : (ks ? g_ZB : g_ZA);

    const int tid = threadIdx.x;
    const int tx = tid & 15, ty = tid >> 4;
    const int i0 = blockIdx.x * 128, j0 = blockIdx.y * 128;
    const int kbase = ks * 384;

    float acc[8][8];
    #pragma unroll
    for (int i = 0; i < 8; ++i)
        #pragma unroll
        for (int j = 0; j < 8; ++j) acc[i][j] = 0.f;

    for (int k0 = kbase; k0 < kbase + 384; k0 += 32) {
        #pragma unroll
        for (int l = 0; l < 16; ++l) {
            int idx = tid + l * 256;
            int r = idx >> 5, kk = idx & 31;
            size_t ai = (size_t)(i0 + r) * EMB + k0 + kk;
            float av;
            if (stage == 0) av = g_P[ai];
            else            av = g_HA[ai] + g_HB[ai] + bias[k0 + kk];
            At[kk * WPITCH + r] = av;
            Bt[kk * WPITCH + r] = B[(size_t)(j0 + r) * EMB + k0 + kk];
        }
        __syncthreads();
        #pragma unroll 8
        for (int kk = 0; kk < 32; ++kk) {
            float4 a0 = *reinterpret_cast<const float4*>(At + kk*WPITCH + ty*4);
            float4 a1 = *reinterpret_cast<const float4*>(At + kk*WPITCH + 64 + ty*4);
            float4 b0 = *reinterpret_cast<const float4*>(Bt + kk*WPITCH + tx*4);
            float4 b1 = *reinterpret_cast<const float4*>(Bt + kk*WPITCH + 64 + tx*4);
            float a[8] = {a0.x,a0.y,a0.z,a0.w,a1.x,a1.y,a1.z,a1.w};
            float b[8] = {b0.x,b0.y,b0.z,b0.w,b1.x,b1.y,b1.z,b1.w};
            #pragma unroll
            for (int i = 0; i < 8; ++i)
                #pragma unroll
                for (int j = 0; j < 8; ++j)
                    acc[i][j] += a[i] * b[j];
        }
        __syncthreads();
    }
    #pragma unroll
    for (int i = 0; i < 8; ++i) {
        int r = i0 + ((i < 4) ? (ty*4 + i) : (64 + ty*4 + (i - 4)));
        #pragma unroll
        for (int j = 0; j < 8; ++j) {
            int cc = (j < 4) ? (tx*4 + j) : (64 + tx*4 + (j - 4));
            C[(size_t)r * EMB + j0 + cc] = acc[i][j];
        }
    }
}

__global__ void combine_kernel(const float* __restrict__ W3, const float* __restrict__ b2,
                               const float* __restrict__ b3, float* __restrict__ out)
{
    __shared__ float red[4];
    const int m = blockIdx.x, tid = threadIdx.x;
    const size_t r1 = (size_t)m * EMB, r2 = (size_t)(MROWS + m) * EMB, r3 = (size_t)(2*MROWS + m) * EMB;
    float acc = 0.f;
    for (int e = tid; e < EMB; e += 128) {
        float bb = b2[e];
        float a = fmaxf(g_ZA[r1 + e] + g_ZB[r1 + e] + bb, 0.f);
        float b = fmaxf(g_ZA[r2 + e] + g_ZB[r2 + e] + bb, 0.f);
        float c = fmaxf(g_ZA[r3 + e] + g_ZB[r3 + e] + bb, 0.f);
        acc += W3[e] * a + W3[EMB + e] * b
             + W3[2*EMB + e] * fabsf(a - b)
             + W3[3*EMB + e] * fabsf(a - c)
             + W3[4*EMB + e] * fabsf(b - c);
    }
    #pragma unroll
    for (int off = 16; off; off >>= 1)
        acc += __shfl_xor_sync(0xffffffffu, acc, off);
    const int lane = tid & 31, warp = tid >> 5;
    if (lane == 0) red[warp] = acc;
    __syncthreads();
    if (tid == 0)
        out[m] = fmaxf(red[0] + red[1] + red[2] + red[3] + b3[0], 0.f);
}

extern "C" void kernel_launch(void* const* d_in, const int* in_sizes, int n_in,
                              void* d_out, int out_size)
{
    const float* X  = (const float*)d_in[0];
    const float* Wa = (const float*)d_in[1];
    const float* va = (const float*)d_in[2];
    const float* W1 = (const float*)d_in[3];
    const float* b1 = (const float*)d_in[4];
    const float* W2 = (const float*)d_in[5];
    const float* b2 = (const float*)d_in[6];
    const float* W3 = (const float*)d_in[7];
    const float* b3 = (const float*)d_in[8];
    float* out = (float*)d_out;

    prep_wa<<<768, 256>>>(Wa);

    cudaFuncSetAttribute(attend_mma, cudaFuncAttributeMaxDynamicSharedMemorySize, SMT);
    attend_mma<<<MROWS, 256, SMT>>>(X, va);

    dim3 g(24, 6, 2);
    mlp_gemm<<<g, 256>>>(0, W1, b1);
    mlp_gemm<<<g, 256>>>(1, W2, b1);
    combine_kernel<<<MROWS, 128>>>(W3, b2, b3, out);
}